// round 1
// baseline (speedup 1.0000x reference)
#include <cuda_runtime.h>
#include <math.h>
#include <stdint.h>

// Problem constants
#define TT   128
#define BB   64
#define DD   1024
#define HH   1024
#define HAA  128
#define VV   10000
#define MM   (TT*BB)   // 8192

// ---------------- scratch (static device memory; no allocs allowed) -------
__device__ float g_Pax[MM*HAA];     // 4 MB : x@Wax + bah
__device__ float g_Pih[(size_t)MM*HH]; // 32 MB : x@Wih + bh
__device__ float g_hs [(size_t)MM*HH]; // 32 MB : h1 history (decode A operand)
__device__ float g_h0 [BB*HAA];     // gate state (tanh'ed)
__device__ float g_h1 [BB*HH];      // current h1
__device__ float g_pre[BB*HH];      // pre-activation of current step
__device__ float g_a  [BB*2];       // (n, s) gates

// ---------------- helpers -------------------------------------------------
__device__ __forceinline__ float f2tf(float x) {
    unsigned r;
    asm("cvt.rna.tf32.f32 %0, %1;" : "=r"(r) : "f"(x));
    return __uint_as_float(r);
}

__device__ __forceinline__ void mma_tf32(float& d0, float& d1, float& d2, float& d3,
                                         unsigned a0, unsigned a1, unsigned a2, unsigned a3,
                                         unsigned b0, unsigned b1) {
    asm volatile(
        "mma.sync.aligned.m16n8k8.row.col.f32.tf32.tf32.f32 "
        "{%0,%1,%2,%3}, {%4,%5,%6,%7}, {%8,%9}, {%0,%1,%2,%3};\n"
        : "+f"(d0), "+f"(d1), "+f"(d2), "+f"(d3)
        : "r"(a0), "r"(a1), "r"(a2), "r"(a3), "r"(b0), "r"(b1));
}

// ---------------- tf32 tiled GEMM: C = rowgather(A) @ W + bias ------------
// CTA tile 128x128, k-step 32. 8 warps = 2(m) x 4(n), warp tile 64x32.
// GATHER=1: A row i = A + tok[i]*K  (embedding gather). GATHER=0: A + i*K.
#define ASTR 36   // padded A smem row stride (floats) -> conflict-free frag reads
#define BSTR 132  // padded B smem row stride

template<int GATHER>
__global__ __launch_bounds__(256)
void gemm_tf32(const float* __restrict__ A, const int* __restrict__ tok,
               const float* __restrict__ W, const float* __restrict__ bias,
               float* __restrict__ C, int M, int N, int K)
{
    __shared__ __align__(16) float As[128*ASTR];
    __shared__ __align__(16) float Bs[32*BSTR];

    const int tid  = threadIdx.x;
    const int row0 = blockIdx.x * 128;
    const int n0   = blockIdx.y * 128;

    const int w    = tid >> 5;
    const int lane = tid & 31;
    const int g    = lane >> 2;   // group id (0..7)
    const int tg   = lane & 3;    // thread in group
    const int wm   = w >> 2;      // 0..1
    const int wn   = w & 3;       // 0..3

    // Per-thread A load slots (4 float4 per k-step): row pointers fixed over k.
    const float* arow[4];
    int asm_off[4];
#pragma unroll
    for (int i = 0; i < 4; i++) {
        int li = tid + 256 * i;
        int r  = li >> 3;            // 0..127
        int kc = (li & 7) * 4;       // 0..28
        int grow = row0 + r;
        size_t src = GATHER ? (size_t)tok[grow] * K : (size_t)grow * K;
        arow[i]    = A + src + kc;
        asm_off[i] = r * ASTR + kc;
    }

    const bool fullN = (n0 + 128 <= N);

    float acc[4][4][4];
#pragma unroll
    for (int mt = 0; mt < 4; mt++)
#pragma unroll
        for (int nt = 0; nt < 4; nt++)
#pragma unroll
            for (int q = 0; q < 4; q++) acc[mt][nt][q] = 0.f;

    for (int kk0 = 0; kk0 < K; kk0 += 32) {
        // --- load A tile (tf32-rounded on store) ---
#pragma unroll
        for (int i = 0; i < 4; i++) {
            float4 v = *reinterpret_cast<const float4*>(arow[i] + kk0);
            float* d = &As[asm_off[i]];
            d[0] = f2tf(v.x); d[1] = f2tf(v.y); d[2] = f2tf(v.z); d[3] = f2tf(v.w);
        }
        // --- load B tile ---
        if (fullN) {
#pragma unroll
            for (int i = 0; i < 4; i++) {
                int li = tid + 256 * i;
                int r  = li >> 5;            // 0..31
                int c4 = (li & 31) * 4;
                float4 v = *reinterpret_cast<const float4*>(W + (size_t)(kk0 + r) * N + n0 + c4);
                float* d = &Bs[r * BSTR + c4];
                d[0] = f2tf(v.x); d[1] = f2tf(v.y); d[2] = f2tf(v.z); d[3] = f2tf(v.w);
            }
        } else {
#pragma unroll
            for (int i = 0; i < 4; i++) {
                int li = tid + 256 * i;
                int r  = li >> 5;
                int c4 = (li & 31) * 4;
#pragma unroll
                for (int q = 0; q < 4; q++) {
                    int col = n0 + c4 + q;
                    float v = (col < N) ? W[(size_t)(kk0 + r) * N + col] : 0.f;
                    Bs[r * BSTR + c4 + q] = f2tf(v);
                }
            }
        }
        __syncthreads();

#pragma unroll
        for (int ks = 0; ks < 4; ks++) {
            unsigned af[4][4], bf[4][2];
#pragma unroll
            for (int mt = 0; mt < 4; mt++) {
                int rm = wm * 64 + mt * 16;
                af[mt][0] = __float_as_uint(As[(rm + g    ) * ASTR + ks * 8 + tg    ]);
                af[mt][1] = __float_as_uint(As[(rm + 8 + g) * ASTR + ks * 8 + tg    ]);
                af[mt][2] = __float_as_uint(As[(rm + g    ) * ASTR + ks * 8 + tg + 4]);
                af[mt][3] = __float_as_uint(As[(rm + 8 + g) * ASTR + ks * 8 + tg + 4]);
            }
#pragma unroll
            for (int nt = 0; nt < 4; nt++) {
                int cb = wn * 32 + nt * 8 + g;
                bf[nt][0] = __float_as_uint(Bs[(ks * 8 + tg    ) * BSTR + cb]);
                bf[nt][1] = __float_as_uint(Bs[(ks * 8 + tg + 4) * BSTR + cb]);
            }
#pragma unroll
            for (int mt = 0; mt < 4; mt++)
#pragma unroll
                for (int nt = 0; nt < 4; nt++)
                    mma_tf32(acc[mt][nt][0], acc[mt][nt][1], acc[mt][nt][2], acc[mt][nt][3],
                             af[mt][0], af[mt][1], af[mt][2], af[mt][3],
                             bf[nt][0], bf[nt][1]);
        }
        __syncthreads();
    }

    // --- epilogue: C = acc + bias ---
#pragma unroll
    for (int mt = 0; mt < 4; mt++) {
        int row = row0 + wm * 64 + mt * 16 + g;
#pragma unroll
        for (int nt = 0; nt < 4; nt++) {
            int col = n0 + wn * 32 + nt * 8 + tg * 2;
            if (col < N) {
                float b0v = bias[col];
                C[(size_t)row * N + col]       = acc[mt][nt][0] + b0v;
                C[(size_t)(row + 8) * N + col] = acc[mt][nt][2] + b0v;
                if (col + 1 < N) {
                    float b1v = bias[col + 1];
                    C[(size_t)row * N + col + 1]       = acc[mt][nt][1] + b1v;
                    C[(size_t)(row + 8) * N + col + 1] = acc[mt][nt][3] + b1v;
                }
            }
        }
    }
}

// ---------------- recurrence step A: combine + gate chain -----------------
// grid 64 (one block per batch row b), 128 threads
__global__ __launch_bounds__(128)
void step_la(int t, const float* __restrict__ Wah,
             const float* __restrict__ Wa, const float* __restrict__ ba)
{
    const int b   = blockIdx.x;
    const int tid = threadIdx.x;
    __shared__ float h0s[HAA];
    __shared__ float red0[128];
    __shared__ float red1[128];

    // 1) combine h1_{t-1} = f(pre_{t-1}, a_{t-1}); write h1 + hs[t-1]
    if (t == 0) {
        for (int k = tid; k < HH; k += 128) g_h1[b * HH + k] = 0.f;
    } else {
        const float n_ = g_a[b * 2 + 0];
        const float s_ = g_a[b * 2 + 1];
        for (int k = tid; k < HH; k += 128) {
            float p = g_pre[b * HH + k];
            float z = n_ * p;
            float th = tanhf(z);
            float sg = 1.f / (1.f + __expf(-z));
            float h  = (1.f - s_) * th + s_ * sg;
            g_h1[b * HH + k] = h;
            g_hs[((size_t)(t - 1) * BB + b) * HH + k] = h;
        }
    }

    // 2) gate state: h0_t = tanh(Pax[t] + h0_{t-1} @ Wah)
    float h0old = (t == 0) ? 0.f : g_h0[b * HAA + tid];
    h0s[tid] = h0old;
    __syncthreads();

    float acc = g_Pax[((size_t)t * BB + b) * HAA + tid];
#pragma unroll 8
    for (int i = 0; i < HAA; i++) acc += h0s[i] * Wah[i * HAA + tid];
    float h0n = tanhf(acc);
    g_h0[b * HAA + tid] = h0n;

    // 3) a_t = sigmoid(h0n @ Wa + ba)
    red0[tid] = h0n * Wa[tid * 2 + 0];
    red1[tid] = h0n * Wa[tid * 2 + 1];
    __syncthreads();
    for (int s = 64; s > 0; s >>= 1) {
        if (tid < s) { red0[tid] += red0[tid + s]; red1[tid] += red1[tid + s]; }
        __syncthreads();
    }
    if (tid == 0) {
        g_a[b * 2 + 0] = 1.f / (1.f + __expf(-(red0[0] + ba[0])));
        g_a[b * 2 + 1] = 1.f / (1.f + __expf(-(red1[0] + ba[1])));
    }
}

// ---------------- recurrence step B: pre_t = Pih[t] + h1 @ Whh ------------
// grid 128 blocks (8 columns each, all 64 batch rows), 256 threads
__global__ __launch_bounds__(256)
void step_lb(int t, const float* __restrict__ Whh)
{
    const int c   = blockIdx.x;
    const int tid = threadIdx.x;
    const int h0c = c * 8;

    __shared__ float h1s[64 * 33];
    __shared__ float ws[32 * 8];

    const int b0 = tid >> 3;   // 0..31
    const int j  = tid & 7;    // 0..7

    float acc0 = g_Pih[((size_t)t * BB + b0     ) * HH + h0c + j];
    float acc1 = g_Pih[((size_t)t * BB + b0 + 32) * HH + h0c + j];

    for (int kk0 = 0; kk0 < HH; kk0 += 32) {
#pragma unroll
        for (int i = 0; i < 8; i++) {
            int li = tid + i * 256;
            int r  = li >> 5;
            int kk = li & 31;
            h1s[r * 33 + kk] = g_h1[r * HH + kk0 + kk];
        }
        {
            int r = tid >> 3, jj = tid & 7;
            ws[tid] = Whh[(size_t)(kk0 + r) * HH + h0c + jj];
        }
        __syncthreads();
#pragma unroll
        for (int kk = 0; kk < 32; kk++) {
            float wv = ws[kk * 8 + j];
            acc0 += h1s[b0 * 33 + kk] * wv;
            acc1 += h1s[(b0 + 32) * 33 + kk] * wv;
        }
        __syncthreads();
    }

    g_pre[b0 * HH + h0c + j]        = acc0;
    g_pre[(b0 + 32) * HH + h0c + j] = acc1;
}

// ---------------- finalize: h1_{T-1} -> hs[T-1] and h1_final --------------
__global__ __launch_bounds__(128)
void finalize_k(float* __restrict__ out_h1, int write_out)
{
    const int b   = blockIdx.x;
    const int tid = threadIdx.x;
    const float n_ = g_a[b * 2 + 0];
    const float s_ = g_a[b * 2 + 1];
    for (int k = tid; k < HH; k += 128) {
        float p = g_pre[b * HH + k];
        float z = n_ * p;
        float h = (1.f - s_) * tanhf(z) + s_ * (1.f / (1.f + __expf(-z)));
        g_hs[((size_t)(TT - 1) * BB + b) * HH + k] = h;
        if (write_out) out_h1[b * HH + k] = h;
    }
}

// ---------------- launch --------------------------------------------------
extern "C" void kernel_launch(void* const* d_in, const int* in_sizes, int n_in,
                              void* d_out, int out_size)
{
    const int*   tokens = (const int*)  d_in[0];
    const float* emb    = (const float*)d_in[1];
    const float* Wax    = (const float*)d_in[2];
    const float* Wah    = (const float*)d_in[3];
    const float* bah    = (const float*)d_in[4];
    const float* Wa     = (const float*)d_in[5];
    const float* ba     = (const float*)d_in[6];
    const float* Wih    = (const float*)d_in[7];
    const float* Whh    = (const float*)d_in[8];
    const float* bh     = (const float*)d_in[9];
    const float* Wd     = (const float*)d_in[10];
    const float* bd     = (const float*)d_in[11];
    float* out = (float*)d_out;

    float *pPax, *pPih, *pHs;
    cudaGetSymbolAddress((void**)&pPax, g_Pax);
    cudaGetSymbolAddress((void**)&pPih, g_Pih);
    cudaGetSymbolAddress((void**)&pHs,  g_hs);

    // Precompute Pax = emb[tok]@Wax + bah ; Pih = emb[tok]@Wih + bh
    gemm_tf32<1><<<dim3(MM / 128, HAA / 128), 256>>>(emb, tokens, Wax, bah, pPax, MM, HAA, DD);
    gemm_tf32<1><<<dim3(MM / 128, HH  / 128), 256>>>(emb, tokens, Wih, bh,  pPih, MM, HH,  DD);

    // Sequential recurrence
    for (int t = 0; t < TT; t++) {
        step_la<<<BB, 128>>>(t, Wah, Wa, ba);
        step_lb<<<128, 256>>>(t, Whh);
    }

    const size_t dec_elems = (size_t)MM * VV;
    int write_h1 = (size_t)out_size >= dec_elems + (size_t)BB * HH;
    finalize_k<<<BB, 128>>>(out + dec_elems, write_h1);

    // Decode: out = hs @ Wd + bd   (M=8192, N=10000, K=1024)
    gemm_tf32<0><<<dim3(MM / 128, (VV + 127) / 128), 256>>>(pHs, nullptr, Wd, bd, out, MM, VV, HH);
}

// round 3
// speedup vs baseline: 3.0810x; 3.0810x over previous
#include <cuda_runtime.h>
#include <math.h>
#include <stdint.h>

// Problem constants
#define TT   128
#define BB   64
#define DD   1024
#define HH   1024
#define HAA  128
#define VV   10000
#define MM   (TT*BB)   // 8192
#define NBLK 65        // persistent kernel blocks: 64 gemm + 1 gate

// ---------------- scratch (static device memory) --------------------------
__device__ __align__(16) float g_Pax[MM*HAA];
__device__ __align__(16) float g_Pih[(size_t)MM*HH];
__device__ __align__(16) float g_hs [(size_t)MM*HH];
__device__ __align__(16) float g_h1 [BB*HH];      // tf32-rounded current h1
__device__ __align__(16) float g_a  [BB*2];
__device__ unsigned g_bar;
__device__ unsigned g_gen;

// ---------------- helpers -------------------------------------------------
__device__ __forceinline__ float f2tf(float x) {
    unsigned r;
    asm("cvt.rna.tf32.f32 %0, %1;" : "=r"(r) : "f"(x));
    return __uint_as_float(r);
}

__device__ __forceinline__ void mma_tf32(float* d,
                                         float a0, float a1, float a2, float a3,
                                         float b0, float b1) {
    asm volatile(
        "mma.sync.aligned.m16n8k8.row.col.f32.tf32.tf32.f32 "
        "{%0,%1,%2,%3}, {%4,%5,%6,%7}, {%8,%9}, {%0,%1,%2,%3};\n"
        : "+f"(d[0]), "+f"(d[1]), "+f"(d[2]), "+f"(d[3])
        : "r"(__float_as_uint(a0)), "r"(__float_as_uint(a1)),
          "r"(__float_as_uint(a2)), "r"(__float_as_uint(a3)),
          "r"(__float_as_uint(b0)), "r"(__float_as_uint(b1)));
}

__device__ __forceinline__ void cp16(float* s, const float* gp) {
    unsigned sa = (unsigned)__cvta_generic_to_shared(s);
    asm volatile("cp.async.ca.shared.global [%0], [%1], 16;\n" :: "r"(sa), "l"(gp));
}

__device__ __forceinline__ float cmb(float p, float n_, float s_) {
    float z = n_ * p;
    return (1.f - s_) * tanhf(z) + s_ * (1.f / (1.f + __expf(-z)));
}

// ---------------- persistent recurrence kernel ----------------------------
// blocks 0..63: pre = Pih[t] + h1@Whh over 16 owned columns; fused combine.
// block 64   : gate chain h0/a.
extern __shared__ float smf[];

#define GBAR() do {                                                          \
    __syncthreads();                                                         \
    if (tid == 0) {                                                          \
        __threadfence();                                                     \
        bcount++;                                                            \
        if (atomicAdd(&g_bar, 1u) == NBLK - 1u) {                            \
            atomicExch(&g_bar, 0u);                                          \
            __threadfence();                                                 \
            atomicAdd(&g_gen, 1u);                                           \
        } else {                                                             \
            while ((int)(atomicAdd(&g_gen, 0u) - (base + bcount)) < 0)       \
                __nanosleep(64);                                             \
        }                                                                    \
        __threadfence();                                                     \
    }                                                                        \
    __syncthreads();                                                         \
} while (0)

__global__ __launch_bounds__(256)
void rnn_persist(const float* __restrict__ Whh, const float* __restrict__ Wah,
                 const float* __restrict__ Wa,  const float* __restrict__ ba,
                 float* __restrict__ out_h1, int write_h1)
{
    const int blk  = blockIdx.x;
    const int tid  = threadIdx.x;
    const int w    = tid >> 5;
    const int lane = tid & 31;
    const int g    = lane >> 2;
    const int tg   = lane & 3;

    unsigned bcount = 0, base = 0;
    if (tid == 0) base = atomicAdd(&g_gen, 0u);

    if (blk < 64) {
        // ================= GEMM block =================
        float* whh  = smf;              // 2 panels [1024][8]
        float* abuf = smf + 16384;      // 2 x [64][68]
        const int n0 = blk * 16;
        const int mt = w >> 1, nt = w & 1, m0 = mt * 16;

        for (int idx = tid; idx < 1024 * 16; idx += 256) {
            int k = idx >> 4, c = idx & 15;
            whh[(c >> 3) * 8192 + k * 8 + (c & 7)] = f2tf(Whh[(size_t)k * HH + n0 + c]);
        }
        for (int i = tid; i < 1024; i += 256) g_h1[blk * 1024 + i] = 0.f;

        GBAR();  // h1(-1)=0 visible everywhere

        for (int t = 0; t < TT; t++) {
            float ac[4][4];
#pragma unroll
            for (int q = 0; q < 4; q++)
#pragma unroll
                for (int r = 0; r < 4; r++) ac[q][r] = 0.f;

            // prologue: chunk 0
            {
                const float* hb = g_h1;
                float* dst = abuf;
#pragma unroll
                for (int i = 0; i < 4; i++) {
                    int li = tid + i * 256, r = li >> 4, c4 = (li & 15) * 4;
                    cp16(dst + r * 68 + c4, hb + (size_t)r * HH + c4);
                }
                asm volatile("cp.async.commit_group;\n");
            }

            for (int ck = 0; ck < 16; ck++) {
                if (ck < 15) {
                    const float* hb = g_h1 + (ck + 1) * 64;
                    float* dst = abuf + ((ck + 1) & 1) * 4352;
#pragma unroll
                    for (int i = 0; i < 4; i++) {
                        int li = tid + i * 256, r = li >> 4, c4 = (li & 15) * 4;
                        cp16(dst + r * 68 + c4, hb + (size_t)r * HH + c4);
                    }
                    asm volatile("cp.async.commit_group;\n");
                    asm volatile("cp.async.wait_group 1;\n");
                } else {
                    asm volatile("cp.async.wait_group 0;\n");
                }
                __syncthreads();

                const float* ab = abuf + (ck & 1) * 4352;
                const float* wp = whh + nt * 8192 + (ck * 64) * 8;
#pragma unroll
                for (int ks = 0; ks < 8; ks++) {
                    int kk = ks * 8;
                    float a0 = ab[(m0 + g) * 68 + kk + tg];
                    float a1 = ab[(m0 + 8 + g) * 68 + kk + tg];
                    float a2 = ab[(m0 + g) * 68 + kk + tg + 4];
                    float a3 = ab[(m0 + 8 + g) * 68 + kk + tg + 4];
                    float b0 = wp[(kk + tg) * 8 + g];
                    float b1 = wp[(kk + tg + 4) * 8 + g];
                    mma_tf32(ac[ks & 3], a0, a1, a2, a3, b0, b1);
                }
                __syncthreads();
            }

            float p0 = ac[0][0] + ac[1][0] + ac[2][0] + ac[3][0];
            float p1 = ac[0][1] + ac[1][1] + ac[2][1] + ac[3][1];
            float p2 = ac[0][2] + ac[1][2] + ac[2][2] + ac[3][2];
            float p3 = ac[0][3] + ac[1][3] + ac[2][3] + ac[3][3];

            const int r0 = m0 + g, r1 = m0 + 8 + g;
            const int c0 = n0 + nt * 8 + tg * 2;
            const float* pih = g_Pih + (size_t)(t * BB) * HH;
            p0 += pih[(size_t)r0 * HH + c0];
            p1 += pih[(size_t)r0 * HH + c0 + 1];
            p2 += pih[(size_t)r1 * HH + c0];
            p3 += pih[(size_t)r1 * HH + c0 + 1];

            GBAR();  // a(t) ready; all h1(t-1) reads done

            float na = g_a[r0 * 2], sa = g_a[r0 * 2 + 1];
            float nb = g_a[r1 * 2], sb = g_a[r1 * 2 + 1];
            float h00 = cmb(p0, na, sa);
            float h01 = cmb(p1, na, sa);
            float h10 = cmb(p2, nb, sb);
            float h11 = cmb(p3, nb, sb);

            float* hsrow = g_hs + (size_t)(t * BB) * HH;
            hsrow[(size_t)r0 * HH + c0]     = f2tf(h00);
            hsrow[(size_t)r0 * HH + c0 + 1] = f2tf(h01);
            hsrow[(size_t)r1 * HH + c0]     = f2tf(h10);
            hsrow[(size_t)r1 * HH + c0 + 1] = f2tf(h11);
            g_h1[r0 * HH + c0]     = f2tf(h00);
            g_h1[r0 * HH + c0 + 1] = f2tf(h01);
            g_h1[r1 * HH + c0]     = f2tf(h10);
            g_h1[r1 * HH + c0 + 1] = f2tf(h11);
            if (write_h1 && t == TT - 1) {
                out_h1[r0 * HH + c0]     = h00;
                out_h1[r0 * HH + c0 + 1] = h01;
                out_h1[r1 * HH + c0]     = h10;
                out_h1[r1 * HH + c0 + 1] = h11;
            }

            GBAR();  // h1(t) visible
        }
    } else {
        // ================= gate block =================
        float* wah = smf;                     // 16 panels [128][8]
        float* h0s = smf + 16384;             // [64][132]
        float* waS = smf + 16384 + 8448;      // [256]
        float* baS = waS + 256;               // [2]

        for (int idx = tid; idx < 128 * 128; idx += 256) {
            int k = idx >> 7, c = idx & 127;
            wah[(c >> 3) * 1024 + k * 8 + (c & 7)] = f2tf(Wah[k * HAA + c]);
        }
        for (int idx = tid; idx < 64 * 132; idx += 256) h0s[idx] = 0.f;
        if (tid < 256) waS[tid] = Wa[tid];
        if (tid < 2)   baS[tid] = ba[tid];

        GBAR();

        for (int t = 0; t < TT; t++) {
            float acg[4][2][4];
#pragma unroll
            for (int mt = 0; mt < 4; mt++)
#pragma unroll
                for (int n = 0; n < 2; n++)
#pragma unroll
                    for (int q = 0; q < 4; q++) acg[mt][n][q] = 0.f;

#pragma unroll
            for (int mt = 0; mt < 4; mt++) {
                int m0g = mt * 16;
#pragma unroll
                for (int ks = 0; ks < 16; ks++) {
                    int kk = ks * 8;
                    float a0 = h0s[(m0g + g) * 132 + kk + tg];
                    float a1 = h0s[(m0g + 8 + g) * 132 + kk + tg];
                    float a2 = h0s[(m0g + g) * 132 + kk + tg + 4];
                    float a3 = h0s[(m0g + 8 + g) * 132 + kk + tg + 4];
#pragma unroll
                    for (int ntl = 0; ntl < 2; ntl++) {
                        const float* wp = wah + (w * 2 + ntl) * 1024;
                        float b0 = wp[(kk + tg) * 8 + g];
                        float b1 = wp[(kk + tg + 4) * 8 + g];
                        mma_tf32(acg[mt][ntl], a0, a1, a2, a3, b0, b1);
                    }
                }
            }
            __syncthreads();  // all reads of old h0s done

            const float* pax = g_Pax + (size_t)(t * BB) * HAA;
#pragma unroll
            for (int mt = 0; mt < 4; mt++) {
#pragma unroll
                for (int ntl = 0; ntl < 2; ntl++) {
                    int m0g = mt * 16;
                    int c0 = (w * 2 + ntl) * 8 + tg * 2;
                    int r0 = m0g + g, r1 = m0g + 8 + g;
                    h0s[r0 * 132 + c0]     = f2tf(tanhf(acg[mt][ntl][0] + pax[r0 * HAA + c0]));
                    h0s[r0 * 132 + c0 + 1] = f2tf(tanhf(acg[mt][ntl][1] + pax[r0 * HAA + c0 + 1]));
                    h0s[r1 * 132 + c0]     = f2tf(tanhf(acg[mt][ntl][2] + pax[r1 * HAA + c0]));
                    h0s[r1 * 132 + c0 + 1] = f2tf(tanhf(acg[mt][ntl][3] + pax[r1 * HAA + c0 + 1]));
                }
            }
            __syncthreads();

            if (tid < 128) {
                int b = tid >> 1, j = tid & 1;
                float s = baS[j];
#pragma unroll 8
                for (int k = 0; k < HAA; k++) s += h0s[b * 132 + k] * waS[k * 2 + j];
                g_a[b * 2 + j] = 1.f / (1.f + __expf(-s));
            }

            GBAR();  // publish a(t)
            GBAR();  // combine done elsewhere
        }
    }
}

// ---------------- tf32 tiled GEMM (prefetch double-buffered) --------------
#define ASTR 36
#define BSTR 132

template<int GATHER>
__global__ __launch_bounds__(256)
void gemm_tf32(const float* __restrict__ A, const int* __restrict__ tok,
               const float* __restrict__ W, const float* __restrict__ bias,
               float* __restrict__ C, int M, int N, int K)
{
    __shared__ __align__(16) float As[128 * ASTR];
    __shared__ __align__(16) float Bs[32 * BSTR];

    const int tid  = threadIdx.x;
    const int row0 = blockIdx.x * 128;
    const int n0   = blockIdx.y * 128;

    const int w    = tid >> 5;
    const int lane = tid & 31;
    const int g    = lane >> 2;
    const int tg   = lane & 3;
    const int wm   = w >> 2;
    const int wn   = w & 3;

    const float* arow[4];
    int asm_off[4];
#pragma unroll
    for (int i = 0; i < 4; i++) {
        int li = tid + 256 * i;
        int r  = li >> 3;
        int kc = (li & 7) * 4;
        int grow = row0 + r;
        size_t src = GATHER ? (size_t)tok[grow] * K : (size_t)grow * K;
        arow[i]    = A + src + kc;
        asm_off[i] = r * ASTR + kc;
    }

    const bool fullN = (n0 + 128 <= N);
    const float* brow[4];
    int bsm[4];
#pragma unroll
    for (int i = 0; i < 4; i++) {
        int li = tid + 256 * i;
        int r  = li >> 5;
        int c4 = (li & 31) * 4;
        brow[i] = W + (size_t)r * N + n0 + c4;
        bsm[i]  = r * BSTR + c4;
    }

    float acc[4][4][4];
#pragma unroll
    for (int mt = 0; mt < 4; mt++)
#pragma unroll
        for (int nt = 0; nt < 4; nt++)
#pragma unroll
            for (int q = 0; q < 4; q++) acc[mt][nt][q] = 0.f;

    float4 ra[4], rb[4];
#pragma unroll
    for (int i = 0; i < 4; i++) ra[i] = *reinterpret_cast<const float4*>(arow[i]);
    if (fullN) {
#pragma unroll
        for (int i = 0; i < 4; i++) rb[i] = *reinterpret_cast<const float4*>(brow[i]);
    }

    for (int kk0 = 0; kk0 < K; kk0 += 32) {
        // store current chunk to smem (tf32-rounded)
#pragma unroll
        for (int i = 0; i < 4; i++) {
            float* d = &As[asm_off[i]];
            d[0] = f2tf(ra[i].x); d[1] = f2tf(ra[i].y);
            d[2] = f2tf(ra[i].z); d[3] = f2tf(ra[i].w);
        }
        if (fullN) {
#pragma unroll
            for (int i = 0; i < 4; i++) {
                float* d = &Bs[bsm[i]];
                d[0] = f2tf(rb[i].x); d[1] = f2tf(rb[i].y);
                d[2] = f2tf(rb[i].z); d[3] = f2tf(rb[i].w);
            }
        } else {
#pragma unroll
            for (int i = 0; i < 4; i++) {
                int li = tid + 256 * i;
                int r  = li >> 5;
                int c4 = (li & 31) * 4;
#pragma unroll
                for (int q = 0; q < 4; q++) {
                    int col = n0 + c4 + q;
                    float v = (col < N) ? W[(size_t)(kk0 + r) * N + col] : 0.f;
                    Bs[r * BSTR + c4 + q] = f2tf(v);
                }
            }
        }
        __syncthreads();

        // prefetch next chunk
        if (kk0 + 32 < K) {
#pragma unroll
            for (int i = 0; i < 4; i++)
                ra[i] = *reinterpret_cast<const float4*>(arow[i] + kk0 + 32);
            if (fullN) {
#pragma unroll
                for (int i = 0; i < 4; i++)
                    rb[i] = *reinterpret_cast<const float4*>(brow[i] + (size_t)(kk0 + 32) * N);
            }
        }

#pragma unroll
        for (int ks = 0; ks < 4; ks++) {
            float af[4][4], bf[4][2];
#pragma unroll
            for (int mt = 0; mt < 4; mt++) {
                int rm = wm * 64 + mt * 16;
                af[mt][0] = As[(rm + g    ) * ASTR + ks * 8 + tg    ];
                af[mt][1] = As[(rm + 8 + g) * ASTR + ks * 8 + tg    ];
                af[mt][2] = As[(rm + g    ) * ASTR + ks * 8 + tg + 4];
                af[mt][3] = As[(rm + 8 + g) * ASTR + ks * 8 + tg + 4];
            }
#pragma unroll
            for (int nt = 0; nt < 4; nt++) {
                int cb = wn * 32 + nt * 8 + g;
                bf[nt][0] = Bs[(ks * 8 + tg    ) * BSTR + cb];
                bf[nt][1] = Bs[(ks * 8 + tg + 4) * BSTR + cb];
            }
#pragma unroll
            for (int mt = 0; mt < 4; mt++)
#pragma unroll
                for (int nt = 0; nt < 4; nt++)
                    mma_tf32(acc[mt][nt],
                             af[mt][0], af[mt][1], af[mt][2], af[mt][3],
                             bf[nt][0], bf[nt][1]);
        }
        __syncthreads();
    }

#pragma unroll
    for (int mt = 0; mt < 4; mt++) {
        int row = row0 + wm * 64 + mt * 16 + g;
#pragma unroll
        for (int nt = 0; nt < 4; nt++) {
            int col = n0 + wn * 32 + nt * 8 + tg * 2;
            if (col < N) {
                float b0v = bias[col];
                C[(size_t)row * N + col]       = acc[mt][nt][0] + b0v;
                C[(size_t)(row + 8) * N + col] = acc[mt][nt][2] + b0v;
                if (col + 1 < N) {
                    float b1v = bias[col + 1];
                    C[(size_t)row * N + col + 1]       = acc[mt][nt][1] + b1v;
                    C[(size_t)(row + 8) * N + col + 1] = acc[mt][nt][3] + b1v;
                }
            }
        }
    }
}

// ---------------- launch --------------------------------------------------
extern "C" void kernel_launch(void* const* d_in, const int* in_sizes, int n_in,
                              void* d_out, int out_size)
{
    const int*   tokens = (const int*)  d_in[0];
    const float* emb    = (const float*)d_in[1];
    const float* Wax    = (const float*)d_in[2];
    const float* Wah    = (const float*)d_in[3];
    const float* bah    = (const float*)d_in[4];
    const float* Wa     = (const float*)d_in[5];
    const float* ba     = (const float*)d_in[6];
    const float* Wih    = (const float*)d_in[7];
    const float* Whh    = (const float*)d_in[8];
    const float* bh     = (const float*)d_in[9];
    const float* Wd     = (const float*)d_in[10];
    const float* bd     = (const float*)d_in[11];
    float* out = (float*)d_out;

    float *pPax, *pPih, *pHs;
    cudaGetSymbolAddress((void**)&pPax, g_Pax);
    cudaGetSymbolAddress((void**)&pPih, g_Pih);
    cudaGetSymbolAddress((void**)&pHs,  g_hs);

    // Precompute Pax = emb[tok]@Wax + bah ; Pih = emb[tok]@Wih + bh
    gemm_tf32<1><<<dim3(MM / 128, HAA / 128), 256>>>(emb, tokens, Wax, bah, pPax, MM, HAA, DD);
    gemm_tf32<1><<<dim3(MM / 128, HH  / 128), 256>>>(emb, tokens, Wih, bh,  pPih, MM, HH,  DD);

    // Persistent recurrence (all 128 steps, 2 global barriers per step)
    const size_t dec_elems = (size_t)MM * VV;
    int write_h1 = (size_t)out_size >= dec_elems + (size_t)BB * HH;
    static int smem_set = 0;
    if (!smem_set) {
        cudaFuncSetAttribute(rnn_persist, cudaFuncAttributeMaxDynamicSharedMemorySize, 101376);
        smem_set = 1;
    }
    rnn_persist<<<NBLK, 256, 101376>>>(Whh, Wah, Wa, ba, out + dec_elems, write_h1);

    // Decode: out = hs @ Wd + bd   (M=8192, N=10000, K=1024)
    gemm_tf32<0><<<dim3(MM / 128, (VV + 127) / 128), 256>>>(pHs, nullptr, Wd, bd, out, MM, VV, HH);
}